// round 13
// baseline (speedup 1.0000x reference)
#include <cuda_runtime.h>
#include <cuda_fp16.h>
#include <math.h>
#include <stdint.h>

#define B_    8192
#define DIN_  1024
#define H_    2048
#define DOUT_ 1024
#define E_    8

// ---------------------------------------------------------------------------
// Scratch (allocation-free __device__ globals)
// ---------------------------------------------------------------------------
#define WPE 16777216ull  // weight elements per expert (5 layers, transposed [N,K])
#define ACT_STRIDE ((size_t)B_ * H_)    // per-expert activation stride (elems)
__device__ unsigned short g_Wh[WPE * E_];            // fp16 weights (all layers, all experts)
__device__ unsigned short g_X[(size_t)B_ * DIN_];    // fp16 input acts (shared)
__device__ unsigned short g_A[ACT_STRIDE * E_];      // fp16 per-expert activations
__device__ unsigned short g_Ch[ACT_STRIDE * E_];     // fp16 per-expert pre-activation h
__device__ float g_C[ACT_STRIDE * E_];               // fp32 per-expert final partials
__device__ float g_gate[(size_t)B_ * E_];

// ---------------------------------------------------------------------------
// PTX helpers
// ---------------------------------------------------------------------------
__device__ __forceinline__ uint32_t smem_to_u32(const void* smem_ptr) {
    uint32_t addr;
    asm("{ .reg .u64 tmp; cvta.to.shared.u64 tmp, %1; cvt.u32.u64 %0, tmp; }"
        : "=r"(addr) : "l"(smem_ptr));
    return addr;
}

#define CP_ASYNC16(dst, src) \
    asm volatile("cp.async.cg.shared.global [%0], [%1], 16;" \
                 :: "r"((uint32_t)(dst)), "l"(src) : "memory")

__device__ __forceinline__ void ldsm_x4(uint32_t* r, uint32_t addr) {
    asm volatile("ldmatrix.sync.aligned.m8n8.x4.shared.b16 {%0,%1,%2,%3}, [%4];"
                 : "=r"(r[0]), "=r"(r[1]), "=r"(r[2]), "=r"(r[3]) : "r"(addr));
}

__device__ __forceinline__ void mma_f16(float* c, const uint32_t* a, const uint32_t* b) {
    asm volatile(
        "mma.sync.aligned.m16n8k16.row.col.f32.f16.f16.f32 "
        "{%0,%1,%2,%3}, {%4,%5,%6,%7}, {%8,%9}, {%0,%1,%2,%3};"
        : "+f"(c[0]), "+f"(c[1]), "+f"(c[2]), "+f"(c[3])
        : "r"(a[0]), "r"(a[1]), "r"(a[2]), "r"(a[3]), "r"(b[0]), "r"(b[1]));
}

// ---------------------------------------------------------------------------
// Gate: softmax(x @ Wg + bg) per row. One warp/row.
// ---------------------------------------------------------------------------
__global__ void gate_kernel(const float* __restrict__ x,
                            const float* __restrict__ Wg,
                            const float* __restrict__ bg) {
    int gwarp = (blockIdx.x * blockDim.x + threadIdx.x) >> 5;
    int lane  = threadIdx.x & 31;
    if (gwarp >= B_) return;
    const float* xr = x + (size_t)gwarp * DIN_;
    float acc[E_];
#pragma unroll
    for (int e = 0; e < E_; e++) acc[e] = 0.f;
    for (int i = lane; i < DIN_; i += 32) {
        float xv = xr[i];
        const float4* w4 = reinterpret_cast<const float4*>(Wg + (size_t)i * E_);
        float4 w0 = w4[0], w1 = w4[1];
        acc[0] += xv * w0.x; acc[1] += xv * w0.y;
        acc[2] += xv * w0.z; acc[3] += xv * w0.w;
        acc[4] += xv * w1.x; acc[5] += xv * w1.y;
        acc[6] += xv * w1.z; acc[7] += xv * w1.w;
    }
#pragma unroll
    for (int e = 0; e < E_; e++) {
#pragma unroll
        for (int o = 16; o > 0; o >>= 1)
            acc[e] += __shfl_xor_sync(0xffffffffu, acc[e], o);
    }
    if (lane == 0) {
        float mx = -1e30f;
#pragma unroll
        for (int e = 0; e < E_; e++) { acc[e] += bg[e]; mx = fmaxf(mx, acc[e]); }
        float s = 0.f;
#pragma unroll
        for (int e = 0; e < E_; e++) { acc[e] = expf(acc[e] - mx); s += acc[e]; }
        float inv = 1.f / s;
#pragma unroll
        for (int e = 0; e < E_; e++) g_gate[(size_t)gwarp * E_ + e] = acc[e] * inv;
    }
}

// ---------------------------------------------------------------------------
// Weight convert+transpose, batched over experts (blockIdx.z):
// W [E,K,N] fp32 -> [E][N,K] fp16 (per-expert stride WPE on output).
// ---------------------------------------------------------------------------
__global__ void wconv_hi(const float* __restrict__ Wbase,
                         unsigned short* __restrict__ Whbase,
                         int K, int N) {
    __shared__ float t[64][33];
    const float* W = Wbase + (size_t)blockIdx.z * K * N;
    unsigned short* Wh = Whbase + (size_t)blockIdx.z * WPE;
    const int n0 = blockIdx.x * 32, k0 = blockIdx.y * 64;
    const int tx = threadIdx.x, ty = threadIdx.y;  // 32x8
#pragma unroll
    for (int r = 0; r < 8; r++) {
        int k = ty + r * 8;
        t[k][tx] = W[(size_t)(k0 + k) * N + n0 + tx];
    }
    __syncthreads();
#pragma unroll
    for (int r = 0; r < 4; r++) {
        int n = ty + r * 8;
        __half h0 = __float2half_rn(t[2 * tx][n]);
        __half h1 = __float2half_rn(t[2 * tx + 1][n]);
        size_t o = (size_t)(n0 + n) * K + k0 + 2 * tx;
        *reinterpret_cast<ushort2*>(&Wh[o]) =
            make_ushort2(__half_as_ushort(h0), __half_as_ushort(h1));
    }
}

// ---------------------------------------------------------------------------
// x convert: fp32 -> fp16.
// ---------------------------------------------------------------------------
__global__ void xconv_kernel(const float* __restrict__ x,
                             unsigned short* __restrict__ X, int n4) {
    int i = blockIdx.x * blockDim.x + threadIdx.x;
    if (i >= n4) return;
    float4 v = reinterpret_cast<const float4*>(x)[i];
    ushort4 o;
    o.x = __half_as_ushort(__float2half_rn(v.x));
    o.y = __half_as_ushort(__float2half_rn(v.y));
    o.z = __half_as_ushort(__float2half_rn(v.z));
    o.w = __half_as_ushort(__float2half_rn(v.w));
    reinterpret_cast<ushort4*>(X)[i] = o;
}

// ---------------------------------------------------------------------------
// Fast mish: tanh(softplus(h)) = (u^2+2u)/(u^2+2u+2), u = e^h.
// ---------------------------------------------------------------------------
__device__ __forceinline__ float mish_fast(float h) {
    if (h > 20.f) return h;
    float u = __expf(h);
    float w = u * (u + 2.f);
    return h * __fdividef(w, w + 2.f);
}

// ---------------------------------------------------------------------------
// mish + LayerNorm + fp16 convert, batched over experts (blockIdx.y).
// Reads fp16 pre-activation h (g_Ch). Row of H_=2048, 256 threads.
// ---------------------------------------------------------------------------
__global__ void mish_ln_cvt_kernel(const unsigned short* __restrict__ Chbase,
                                   unsigned short* __restrict__ Abase) {
    __shared__ float sred[64];
    const int t = threadIdx.x;
    const size_t rowoff = ((size_t)blockIdx.y * B_ + blockIdx.x) * H_;
    // 8 halves per thread (16 bytes)
    const uint4 vv = *reinterpret_cast<const uint4*>(Chbase + rowoff + t * 8);
    float vals[8];
    {
        const uint32_t w0 = vv.x, w1 = vv.y, w2 = vv.z, w3 = vv.w;
        float2 p0 = __half22float2(*reinterpret_cast<const __half2*>(&w0));
        float2 p1 = __half22float2(*reinterpret_cast<const __half2*>(&w1));
        float2 p2 = __half22float2(*reinterpret_cast<const __half2*>(&w2));
        float2 p3 = __half22float2(*reinterpret_cast<const __half2*>(&w3));
        vals[0] = p0.x; vals[1] = p0.y; vals[2] = p1.x; vals[3] = p1.y;
        vals[4] = p2.x; vals[5] = p2.y; vals[6] = p3.x; vals[7] = p3.y;
    }
    float s = 0.f, q = 0.f;
#pragma unroll
    for (int i = 0; i < 8; i++) {
        float m = mish_fast(vals[i]);
        vals[i] = m;
        s += m;
        q += m * m;
    }
#pragma unroll
    for (int o = 16; o > 0; o >>= 1) {
        s += __shfl_xor_sync(0xffffffffu, s, o);
        q += __shfl_xor_sync(0xffffffffu, q, o);
    }
    const int w = t >> 5;
    if ((t & 31) == 0) { sred[w] = s; sred[w + 32] = q; }
    __syncthreads();
    if (t < 32) {
        float rs = (t < 8) ? sred[t] : 0.f;
        float rq = (t < 8) ? sred[t + 32] : 0.f;
#pragma unroll
        for (int o = 4; o > 0; o >>= 1) {
            rs += __shfl_xor_sync(0xffffffffu, rs, o);
            rq += __shfl_xor_sync(0xffffffffu, rq, o);
        }
        if (t == 0) { sred[0] = rs; sred[32] = rq; }
    }
    __syncthreads();
    const float mu = sred[0] * (1.f / H_);
    const float var = sred[32] * (1.f / H_) - mu * mu;
    const float inv = rsqrtf(var + 1e-5f);
    unsigned short h8[8];
#pragma unroll
    for (int i = 0; i < 8; i++)
        h8[i] = __half_as_ushort(__float2half_rn((vals[i] - mu) * inv));
    *reinterpret_cast<ushort4*>(Abase + rowoff + t * 8) =
        make_ushort4(h8[0], h8[1], h8[2], h8[3]);
    *reinterpret_cast<ushort4*>(Abase + rowoff + t * 8 + 4) =
        make_ushort4(h8[4], h8[5], h8[6], h8[7]);
}

// ---------------------------------------------------------------------------
// GEMM geometry (validated R12 config): CTA 128x128, 8 warps (2 M x 4 N),
// warp tile 64x32, K-chunk 32, STRIDE 80B, 2 CTAs/SM, pipeline depth 5.
// ---------------------------------------------------------------------------
#define STRIDE_B 80                       // padded row stride in bytes
#define MAT_BYTES (128 * STRIDE_B)        // 10240
#define STAGE_BYTES (2 * MAT_BYTES)       // 20480 (A, Wh)
#define NSTAGE 5
#define SGL_SMEM (NSTAGE * STAGE_BYTES)   // 102400

__device__ __forceinline__ void copy_stage2(uint32_t st, int tid, int kc, int K,
                                            const unsigned short* a,
                                            const unsigned short* bh) {
    const unsigned short* srcs[2] = {a, bh};
#pragma unroll
    for (int m = 0; m < 2; m++) {
#pragma unroll
        for (int q = 0; q < 2; q++) {
            int c = tid * 2 + q;          // 0..511
            int row = c >> 2;             // 0..127
            int kch = c & 3;              // 16B chunk within the 64B row
            uint32_t dst = st + m * MAT_BYTES + row * STRIDE_B + kch * 16;
            const unsigned short* src = srcs[m] + (size_t)row * K + kc * 32 + kch * 8;
            CP_ASYNC16(dst, src);
        }
    }
    asm volatile("cp.async.commit_group;" ::: "memory");
}

// ---------------------------------------------------------------------------
// Single-pass fp16 GEMM, batched over experts (blockIdx.z).
// MODE 0: Ch[z] = fp16(A[z]@W[z]^T + bias[z])    (fp16 output for mish)
// MODE 1: C[z]  = gate[row,z] * (A[z]@W[z]^T + bias[z])  (fp32 partials)
// strideA = 0 lets all experts share one input (L1 / X).
// ---------------------------------------------------------------------------
template <int MODE>
__global__ __launch_bounds__(256, 2)
void tc_gemm_single(const unsigned short* __restrict__ Ag,
                    const unsigned short* __restrict__ Wg,
                    const float* __restrict__ biasg, void* __restrict__ Cg,
                    int N, int K, size_t strideA) {
    extern __shared__ __align__(16) char dynsmem[];
    const uint32_t sbase = smem_to_u32(dynsmem);
    const int tid = threadIdx.x;
    const int wid = tid >> 5, lane = tid & 31;
    const int wm = wid & 1, wn = wid >> 1;   // 2 warps M x 4 warps N
    const int KT = K >> 5;                   // 32 fp16 per chunk
    const int ez = blockIdx.z;

    const unsigned short* a  = Ag + (size_t)ez * strideA + (size_t)(blockIdx.y * 128) * K;
    const unsigned short* bh = Wg + (size_t)ez * WPE + (size_t)(blockIdx.x * 128) * K;
    const float* bias = biasg + (size_t)ez * N;

    float acc[4][4][4];
#pragma unroll
    for (int i = 0; i < 4; i++)
#pragma unroll
        for (int j = 0; j < 4; j++)
#pragma unroll
            for (int q = 0; q < 4; q++) acc[i][j][q] = 0.f;

    // Prologue: fill 4 of 5 stages
    copy_stage2(sbase + 0 * STAGE_BYTES, tid, 0, K, a, bh);
    copy_stage2(sbase + 1 * STAGE_BYTES, tid, 1, K, a, bh);
    copy_stage2(sbase + 2 * STAGE_BYTES, tid, 2, K, a, bh);
    copy_stage2(sbase + 3 * STAGE_BYTES, tid, 3, K, a, bh);

    const uint32_t a_row = wm * 64 + (lane & 15);
    const uint32_t a_koff = (lane >> 4) * 16;
    const uint32_t b_row = wn * 32 + (lane >> 4) * 8 + (lane & 7);
    const uint32_t b_koff = ((lane >> 3) & 1) * 16;

    int scur = 0;   // kc % 5
    int sref = 4;   // (kc+4) % 5
    for (int kc = 0; kc < KT; kc++) {
        if (kc + 3 < KT)      asm volatile("cp.async.wait_group 3;" ::: "memory");
        else if (kc + 2 < KT) asm volatile("cp.async.wait_group 2;" ::: "memory");
        else if (kc + 1 < KT) asm volatile("cp.async.wait_group 1;" ::: "memory");
        else                  asm volatile("cp.async.wait_group 0;" ::: "memory");
        __syncthreads();
        // Stage (kc-1)%5 == (kc+4)%5 fully consumed before the barrier -> refill.
        if (kc + 4 < KT)
            copy_stage2(sbase + sref * STAGE_BYTES, tid, kc + 4, K, a, bh);

        const uint32_t st = sbase + scur * STAGE_BYTES;
#pragma unroll
        for (int h = 0; h < 2; h++) {     // two k16 halves of the 32-elem chunk
            const uint32_t kbyte = h * 32;
            uint32_t fa[16], fbh[8];
#pragma unroll
            for (int i = 0; i < 4; i++)
                ldsm_x4(&fa[i * 4], st + (a_row + i * 16) * STRIDE_B + kbyte + a_koff);
#pragma unroll
            for (int p = 0; p < 2; p++)
                ldsm_x4(&fbh[p * 4],
                        st + MAT_BYTES + (b_row + p * 16) * STRIDE_B + kbyte + b_koff);
#pragma unroll
            for (int i = 0; i < 4; i++)
#pragma unroll
                for (int j = 0; j < 4; j++)
                    mma_f16(acc[i][j], &fa[i * 4], &fbh[(j >> 1) * 4 + (j & 1) * 2]);
        }
        scur = (scur == 4) ? 0 : scur + 1;
        sref = (sref == 4) ? 0 : sref + 1;
    }

    const int r0 = blockIdx.y * 128 + wm * 64 + (lane >> 2);
    const int cbase = blockIdx.x * 128 + wn * 32 + (lane & 3) * 2;
#pragma unroll
    for (int i = 0; i < 4; i++) {
        const int rowA = r0 + i * 16;
        const int rowB = rowA + 8;
        float gA = 1.f, gB = 1.f;
        if (MODE == 1) {
            gA = g_gate[(size_t)rowA * E_ + ez];
            gB = g_gate[(size_t)rowB * E_ + ez];
        }
#pragma unroll
        for (int j = 0; j < 4; j++) {
            const int col = cbase + j * 8;
            float b0 = bias[col], b1 = bias[col + 1];
            if (MODE == 0) {
                unsigned short* Ch = (unsigned short*)Cg + (size_t)ez * ACT_STRIDE;
                __half2 hA = __floats2half2_rn(acc[i][j][0] + b0, acc[i][j][1] + b1);
                __half2 hB = __floats2half2_rn(acc[i][j][2] + b0, acc[i][j][3] + b1);
                *reinterpret_cast<__half2*>(Ch + (size_t)rowA * N + col) = hA;
                *reinterpret_cast<__half2*>(Ch + (size_t)rowB * N + col) = hB;
            } else {
                float* C = (float*)Cg + (size_t)ez * ACT_STRIDE;
                *reinterpret_cast<float2*>(C + (size_t)rowA * N + col) =
                    make_float2(gA * (acc[i][j][0] + b0), gA * (acc[i][j][1] + b1));
                *reinterpret_cast<float2*>(C + (size_t)rowB * N + col) =
                    make_float2(gB * (acc[i][j][2] + b0), gB * (acc[i][j][3] + b1));
            }
        }
    }
}

// ---------------------------------------------------------------------------
// Combine: out = sum over experts of gated fp32 partials Y[e].
// ---------------------------------------------------------------------------
__global__ void combine_kernel(const float* __restrict__ Cbase,
                               float* __restrict__ out, int n4) {
    int i = blockIdx.x * blockDim.x + threadIdx.x;
    if (i >= n4) return;
    float4 s = make_float4(0.f, 0.f, 0.f, 0.f);
#pragma unroll
    for (int e = 0; e < E_; e++) {
        float4 v = *reinterpret_cast<const float4*>(Cbase + (size_t)e * ACT_STRIDE + i * 4);
        s.x += v.x; s.y += v.y; s.z += v.z; s.w += v.w;
    }
    reinterpret_cast<float4*>(out)[i] = s;
}

// ---------------------------------------------------------------------------
// Launch
// ---------------------------------------------------------------------------
extern "C" void kernel_launch(void* const* d_in, const int* in_sizes, int n_in,
                              void* d_out, int out_size) {
    const float* x  = (const float*)d_in[0];
    const float* Wg = (const float*)d_in[1];
    const float* bg = (const float*)d_in[2];
    const float* W1 = (const float*)d_in[3];
    const float* b1 = (const float*)d_in[4];
    const float* W2 = (const float*)d_in[5];
    const float* b2 = (const float*)d_in[6];
    const float* W3 = (const float*)d_in[7];
    const float* b3 = (const float*)d_in[8];
    const float* W4 = (const float*)d_in[9];
    const float* b4 = (const float*)d_in[10];
    const float* W5 = (const float*)d_in[11];
    const float* b5 = (const float*)d_in[12];
    float* out = (float*)d_out;

    void *pWh, *pX, *pA, *pCh, *pC;
    cudaGetSymbolAddress(&pWh, g_Wh);
    cudaGetSymbolAddress(&pX, g_X);
    cudaGetSymbolAddress(&pA, g_A);
    cudaGetSymbolAddress(&pCh, g_Ch);
    cudaGetSymbolAddress(&pC, g_C);
    unsigned short* Wh = (unsigned short*)pWh;
    unsigned short* X = (unsigned short*)pX;
    unsigned short* A = (unsigned short*)pA;
    unsigned short* Ch = (unsigned short*)pCh;
    float* Cbuf = (float*)pC;

    cudaFuncSetAttribute(tc_gemm_single<0>, cudaFuncAttributeMaxDynamicSharedMemorySize, SGL_SMEM);
    cudaFuncSetAttribute(tc_gemm_single<1>, cudaFuncAttributeMaxDynamicSharedMemorySize, SGL_SMEM);

    // Per-expert layer offsets within g_Wh ([N,K] packed, stride WPE per expert)
    const size_t off1 = 0;
    const size_t off2 = off1 + (size_t)DIN_ * H_;
    const size_t off3 = off2 + (size_t)H_ * H_;
    const size_t off4 = off3 + (size_t)H_ * H_;
    const size_t off5 = off4 + (size_t)H_ * H_;

    const dim3 wblk(32, 8);
    const dim3 gridH(H_ / 128, B_ / 128, E_);
    const dim3 gridO(DOUT_ / 128, B_ / 128, E_);
    const dim3 gridM(B_, E_);

    // Launch order (ncu -s 5 -c 1 profiles index 5 = batched L1 GEMM):
    // 0 xconv, 1 wconv L1, 2 gate, 3 wconv L2, 4 wconv L3, 5 gemm L1,
    // 6 mish, 7 wconv L4, 8 wconv L5, 9 gemm L2, 10 mish, 11 gemm L3,
    // 12 mish, 13 gemm L4, 14 mish, 15 gemm L5, 16 combine.
    xconv_kernel<<<(B_ * DIN_ / 4 + 255) / 256, 256>>>(x, X, B_ * DIN_ / 4);
    wconv_hi<<<dim3(H_ / 32, DIN_ / 64, E_), wblk>>>(W1, Wh + off1, DIN_, H_);
    gate_kernel<<<B_ / 8, 256>>>(x, Wg, bg);
    wconv_hi<<<dim3(H_ / 32, H_ / 64, E_), wblk>>>(W2, Wh + off2, H_, H_);
    wconv_hi<<<dim3(H_ / 32, H_ / 64, E_), wblk>>>(W3, Wh + off3, H_, H_);

    tc_gemm_single<0><<<gridH, 256, SGL_SMEM>>>(X, Wh + off1, b1, Ch, H_, DIN_, 0);
    mish_ln_cvt_kernel<<<gridM, 256>>>(Ch, A);

    wconv_hi<<<dim3(H_ / 32, H_ / 64, E_), wblk>>>(W4, Wh + off4, H_, H_);
    wconv_hi<<<dim3(DOUT_ / 32, H_ / 64, E_), wblk>>>(W5, Wh + off5, H_, DOUT_);

    tc_gemm_single<0><<<gridH, 256, SGL_SMEM>>>(A, Wh + off2, b2, Ch, H_, H_, ACT_STRIDE);
    mish_ln_cvt_kernel<<<gridM, 256>>>(Ch, A);
    tc_gemm_single<0><<<gridH, 256, SGL_SMEM>>>(A, Wh + off3, b3, Ch, H_, H_, ACT_STRIDE);
    mish_ln_cvt_kernel<<<gridM, 256>>>(Ch, A);
    tc_gemm_single<0><<<gridH, 256, SGL_SMEM>>>(A, Wh + off4, b4, Ch, H_, H_, ACT_STRIDE);
    mish_ln_cvt_kernel<<<gridM, 256>>>(Ch, A);
    tc_gemm_single<1><<<gridO, 256, SGL_SMEM>>>(A, Wh + off5, b5, Cbuf, DOUT_, H_, ACT_STRIDE);

    combine_kernel<<<(B_ * DOUT_ / 4 + 255) / 256, 256>>>(Cbuf, out, B_ * DOUT_ / 4);
}

// round 14
// speedup vs baseline: 1.5548x; 1.5548x over previous
#include <cuda_runtime.h>
#include <cuda_fp16.h>
#include <math.h>
#include <stdint.h>

#define B_    8192
#define DIN_  1024
#define H_    2048
#define DOUT_ 1024
#define E_    8

// ---------------------------------------------------------------------------
// Scratch (allocation-free __device__ globals)
// ---------------------------------------------------------------------------
#define WPE 16777216ull  // weight elements per expert (5 layers, transposed [N,K])
#define ACT_STRIDE ((size_t)B_ * H_)    // per-expert activation stride (elems)
__device__ unsigned short g_Wh[WPE * E_];            // fp16 weights (all layers, all experts)
__device__ unsigned short g_X[(size_t)B_ * DIN_];    // fp16 input acts (shared)
__device__ unsigned short g_A[ACT_STRIDE * E_];      // fp16 per-expert activations
__device__ float g_C[ACT_STRIDE * E_];               // fp32 per-expert GEMM out / final Y
__device__ float g_gate[(size_t)B_ * E_];

// ---------------------------------------------------------------------------
// PTX helpers
// ---------------------------------------------------------------------------
__device__ __forceinline__ uint32_t smem_to_u32(const void* smem_ptr) {
    uint32_t addr;
    asm("{ .reg .u64 tmp; cvta.to.shared.u64 tmp, %1; cvt.u32.u64 %0, tmp; }"
        : "=r"(addr) : "l"(smem_ptr));
    return addr;
}

#define CP_ASYNC16(dst, src) \
    asm volatile("cp.async.cg.shared.global [%0], [%1], 16;" \
                 :: "r"((uint32_t)(dst)), "l"(src) : "memory")

__device__ __forceinline__ void ldsm_x4(uint32_t* r, uint32_t addr) {
    asm volatile("ldmatrix.sync.aligned.m8n8.x4.shared.b16 {%0,%1,%2,%3}, [%4];"
                 : "=r"(r[0]), "=r"(r[1]), "=r"(r[2]), "=r"(r[3]) : "r"(addr));
}

__device__ __forceinline__ void mma_f16(float* c, const uint32_t* a, const uint32_t* b) {
    asm volatile(
        "mma.sync.aligned.m16n8k16.row.col.f32.f16.f16.f32 "
        "{%0,%1,%2,%3}, {%4,%5,%6,%7}, {%8,%9}, {%0,%1,%2,%3};"
        : "+f"(c[0]), "+f"(c[1]), "+f"(c[2]), "+f"(c[3])
        : "r"(a[0]), "r"(a[1]), "r"(a[2]), "r"(a[3]), "r"(b[0]), "r"(b[1]));
}

// ---------------------------------------------------------------------------
// Gate: softmax(x @ Wg + bg) per row. One warp/row.
// ---------------------------------------------------------------------------
__global__ void gate_kernel(const float* __restrict__ x,
                            const float* __restrict__ Wg,
                            const float* __restrict__ bg) {
    int gwarp = (blockIdx.x * blockDim.x + threadIdx.x) >> 5;
    int lane  = threadIdx.x & 31;
    if (gwarp >= B_) return;
    const float* xr = x + (size_t)gwarp * DIN_;
    float acc[E_];
#pragma unroll
    for (int e = 0; e < E_; e++) acc[e] = 0.f;
    for (int i = lane; i < DIN_; i += 32) {
        float xv = xr[i];
        const float4* w4 = reinterpret_cast<const float4*>(Wg + (size_t)i * E_);
        float4 w0 = w4[0], w1 = w4[1];
        acc[0] += xv * w0.x; acc[1] += xv * w0.y;
        acc[2] += xv * w0.z; acc[3] += xv * w0.w;
        acc[4] += xv * w1.x; acc[5] += xv * w1.y;
        acc[6] += xv * w1.z; acc[7] += xv * w1.w;
    }
#pragma unroll
    for (int e = 0; e < E_; e++) {
#pragma unroll
        for (int o = 16; o > 0; o >>= 1)
            acc[e] += __shfl_xor_sync(0xffffffffu, acc[e], o);
    }
    if (lane == 0) {
        float mx = -1e30f;
#pragma unroll
        for (int e = 0; e < E_; e++) { acc[e] += bg[e]; mx = fmaxf(mx, acc[e]); }
        float s = 0.f;
#pragma unroll
        for (int e = 0; e < E_; e++) { acc[e] = expf(acc[e] - mx); s += acc[e]; }
        float inv = 1.f / s;
#pragma unroll
        for (int e = 0; e < E_; e++) g_gate[(size_t)gwarp * E_ + e] = acc[e] * inv;
    }
}

// ---------------------------------------------------------------------------
// Weight convert+transpose, batched over experts (blockIdx.z):
// W [E,K,N] fp32 -> [E][N,K] fp16 (per-expert stride WPE on output).
// ---------------------------------------------------------------------------
__global__ void wconv_hi(const float* __restrict__ Wbase,
                         unsigned short* __restrict__ Whbase,
                         int K, int N) {
    __shared__ float t[64][33];
    const float* W = Wbase + (size_t)blockIdx.z * K * N;
    unsigned short* Wh = Whbase + (size_t)blockIdx.z * WPE;
    const int n0 = blockIdx.x * 32, k0 = blockIdx.y * 64;
    const int tx = threadIdx.x, ty = threadIdx.y;  // 32x8
#pragma unroll
    for (int r = 0; r < 8; r++) {
        int k = ty + r * 8;
        t[k][tx] = W[(size_t)(k0 + k) * N + n0 + tx];
    }
    __syncthreads();
#pragma unroll
    for (int r = 0; r < 4; r++) {
        int n = ty + r * 8;
        __half h0 = __float2half_rn(t[2 * tx][n]);
        __half h1 = __float2half_rn(t[2 * tx + 1][n]);
        size_t o = (size_t)(n0 + n) * K + k0 + 2 * tx;
        *reinterpret_cast<ushort2*>(&Wh[o]) =
            make_ushort2(__half_as_ushort(h0), __half_as_ushort(h1));
    }
}

// ---------------------------------------------------------------------------
// x convert: fp32 -> fp16.
// ---------------------------------------------------------------------------
__global__ void xconv_kernel(const float* __restrict__ x,
                             unsigned short* __restrict__ X, int n4) {
    int i = blockIdx.x * blockDim.x + threadIdx.x;
    if (i >= n4) return;
    float4 v = reinterpret_cast<const float4*>(x)[i];
    ushort4 o;
    o.x = __half_as_ushort(__float2half_rn(v.x));
    o.y = __half_as_ushort(__float2half_rn(v.y));
    o.z = __half_as_ushort(__float2half_rn(v.z));
    o.w = __half_as_ushort(__float2half_rn(v.w));
    reinterpret_cast<ushort4*>(X)[i] = o;
}

// ---------------------------------------------------------------------------
// Fast mish: tanh(softplus(h)) = (u^2+2u)/(u^2+2u+2), u = e^h.
// ---------------------------------------------------------------------------
__device__ __forceinline__ float mish_fast(float h) {
    if (h > 20.f) return h;
    float u = __expf(h);
    float w = u * (u + 2.f);
    return h * __fdividef(w, w + 2.f);
}

// ---------------------------------------------------------------------------
// mish + LayerNorm + fp16 convert, batched over experts (blockIdx.y).
// Row of H_=2048, 256 threads.
// ---------------------------------------------------------------------------
__global__ void mish_ln_cvt_kernel(const float* __restrict__ Cbase,
                                   unsigned short* __restrict__ Abase) {
    __shared__ float sred[64];
    const int t = threadIdx.x;
    const size_t rowoff = ((size_t)blockIdx.y * B_ + blockIdx.x) * H_;
    const float4* p = reinterpret_cast<const float4*>(Cbase + rowoff);
    float4 v0 = p[t], v1 = p[t + 256];
    float vals[8] = {v0.x, v0.y, v0.z, v0.w, v1.x, v1.y, v1.z, v1.w};
    float s = 0.f, q = 0.f;
#pragma unroll
    for (int i = 0; i < 8; i++) {
        float m = mish_fast(vals[i]);
        vals[i] = m;
        s += m;
        q += m * m;
    }
#pragma unroll
    for (int o = 16; o > 0; o >>= 1) {
        s += __shfl_xor_sync(0xffffffffu, s, o);
        q += __shfl_xor_sync(0xffffffffu, q, o);
    }
    const int w = t >> 5;
    if ((t & 31) == 0) { sred[w] = s; sred[w + 32] = q; }
    __syncthreads();
    if (t < 32) {
        float rs = (t < 8) ? sred[t] : 0.f;
        float rq = (t < 8) ? sred[t + 32] : 0.f;
#pragma unroll
        for (int o = 4; o > 0; o >>= 1) {
            rs += __shfl_xor_sync(0xffffffffu, rs, o);
            rq += __shfl_xor_sync(0xffffffffu, rq, o);
        }
        if (t == 0) { sred[0] = rs; sred[32] = rq; }
    }
    __syncthreads();
    const float mu = sred[0] * (1.f / H_);
    const float var = sred[32] * (1.f / H_) - mu * mu;
    const float inv = rsqrtf(var + 1e-5f);
    unsigned short h8[8];
#pragma unroll
    for (int i = 0; i < 8; i++)
        h8[i] = __half_as_ushort(__float2half_rn((vals[i] - mu) * inv));
    ushort4* oa = reinterpret_cast<ushort4*>(Abase + rowoff);
    oa[t]       = make_ushort4(h8[0], h8[1], h8[2], h8[3]);
    oa[t + 256] = make_ushort4(h8[4], h8[5], h8[6], h8[7]);
}

// ---------------------------------------------------------------------------
// GEMM geometry (validated R12 config): CTA 128x128, 8 warps (2 M x 4 N),
// warp tile 64x32, K-chunk 32, STRIDE 80B, 2 CTAs/SM. Pipeline depth 5.
// ---------------------------------------------------------------------------
#define STRIDE_B 80                       // padded row stride in bytes
#define MAT_BYTES (128 * STRIDE_B)        // 10240
#define STAGE_BYTES (2 * MAT_BYTES)       // 20480 (A, Wh)
#define NSTAGE 5
#define SGL_SMEM (NSTAGE * STAGE_BYTES)   // 102400

__device__ __forceinline__ void copy_stage2(uint32_t st, int tid, int kc, int K,
                                            const unsigned short* a,
                                            const unsigned short* bh) {
    const unsigned short* srcs[2] = {a, bh};
#pragma unroll
    for (int m = 0; m < 2; m++) {
#pragma unroll
        for (int q = 0; q < 2; q++) {
            int c = tid * 2 + q;          // 0..511
            int row = c >> 2;             // 0..127
            int kch = c & 3;              // 16B chunk within the 64B row
            uint32_t dst = st + m * MAT_BYTES + row * STRIDE_B + kch * 16;
            const unsigned short* src = srcs[m] + (size_t)row * K + kc * 32 + kch * 8;
            CP_ASYNC16(dst, src);
        }
    }
    asm volatile("cp.async.commit_group;" ::: "memory");
}

// ---------------------------------------------------------------------------
// Single-pass fp16 GEMM, batched over experts (blockIdx.z).
// MODE 0: C[z] = A[z]@W[z]^T + bias[z]
// MODE 1: C[z] = gate[row,z] * (A[z]@W[z]^T + bias[z])
// strideA = 0 lets all experts share one input (L1 / X).
// ---------------------------------------------------------------------------
template <int MODE>
__global__ __launch_bounds__(256, 2)
void tc_gemm_single(const unsigned short* __restrict__ Ag,
                    const unsigned short* __restrict__ Wg,
                    const float* __restrict__ biasg, float* __restrict__ Cg,
                    int N, int K, size_t strideA) {
    extern __shared__ __align__(16) char dynsmem[];
    const uint32_t sbase = smem_to_u32(dynsmem);
    const int tid = threadIdx.x;
    const int wid = tid >> 5, lane = tid & 31;
    const int wm = wid & 1, wn = wid >> 1;   // 2 warps M x 4 warps N
    const int KT = K >> 5;                   // 32 fp16 per chunk (KT >= 32)
    const int ez = blockIdx.z;

    const unsigned short* a  = Ag + (size_t)ez * strideA + (size_t)(blockIdx.y * 128) * K;
    const unsigned short* bh = Wg + (size_t)ez * WPE + (size_t)(blockIdx.x * 128) * K;
    const float* bias = biasg + (size_t)ez * N;
    float* C = Cg + (size_t)ez * ACT_STRIDE;

    float acc[4][4][4];
#pragma unroll
    for (int i = 0; i < 4; i++)
#pragma unroll
        for (int j = 0; j < 4; j++)
#pragma unroll
            for (int q = 0; q < 4; q++) acc[i][j][q] = 0.f;

    // Prologue: fill 4 of 5 stages
    copy_stage2(sbase + 0 * STAGE_BYTES, tid, 0, K, a, bh);
    copy_stage2(sbase + 1 * STAGE_BYTES, tid, 1, K, a, bh);
    copy_stage2(sbase + 2 * STAGE_BYTES, tid, 2, K, a, bh);
    copy_stage2(sbase + 3 * STAGE_BYTES, tid, 3, K, a, bh);

    const uint32_t a_row = wm * 64 + (lane & 15);
    const uint32_t a_koff = (lane >> 4) * 16;
    const uint32_t b_row = wn * 32 + (lane >> 4) * 8 + (lane & 7);
    const uint32_t b_koff = ((lane >> 3) & 1) * 16;

    int scur = 0;   // kc % 5
    int sref = 4;   // (kc+4) % 5
    for (int kc = 0; kc < KT; kc++) {
        if (kc + 3 < KT)      asm volatile("cp.async.wait_group 3;" ::: "memory");
        else if (kc + 2 < KT) asm volatile("cp.async.wait_group 2;" ::: "memory");
        else if (kc + 1 < KT) asm volatile("cp.async.wait_group 1;" ::: "memory");
        else                  asm volatile("cp.async.wait_group 0;" ::: "memory");
        __syncthreads();
        // Stage (kc-1)%5 == (kc+4)%5 fully consumed before the barrier -> refill.
        if (kc + 4 < KT)
            copy_stage2(sbase + sref * STAGE_BYTES, tid, kc + 4, K, a, bh);

        const uint32_t st = sbase + scur * STAGE_BYTES;
#pragma unroll
        for (int h = 0; h < 2; h++) {     // two k16 halves of the 32-elem chunk
            const uint32_t kbyte = h * 32;
            uint32_t fa[16], fbh[8];
#pragma unroll
            for (int i = 0; i < 4; i++)
                ldsm_x4(&fa[i * 4], st + (a_row + i * 16) * STRIDE_B + kbyte + a_koff);
#pragma unroll
            for (int p = 0; p < 2; p++)
                ldsm_x4(&fbh[p * 4],
                        st + MAT_BYTES + (b_row + p * 16) * STRIDE_B + kbyte + b_koff);
#pragma unroll
            for (int i = 0; i < 4; i++)
#pragma unroll
                for (int j = 0; j < 4; j++)
                    mma_f16(acc[i][j], &fa[i * 4], &fbh[(j >> 1) * 4 + (j & 1) * 2]);
        }
        scur = (scur == 4) ? 0 : scur + 1;
        sref = (sref == 4) ? 0 : sref + 1;
    }

    const int r0 = blockIdx.y * 128 + wm * 64 + (lane >> 2);
    const int cbase = blockIdx.x * 128 + wn * 32 + (lane & 3) * 2;
#pragma unroll
    for (int i = 0; i < 4; i++) {
        const int rowA = r0 + i * 16;
        const int rowB = rowA + 8;
        float gA = 1.f, gB = 1.f;
        if (MODE == 1) {
            gA = g_gate[(size_t)rowA * E_ + ez];
            gB = g_gate[(size_t)rowB * E_ + ez];
        }
#pragma unroll
        for (int j = 0; j < 4; j++) {
            const int col = cbase + j * 8;
            float b0 = bias[col], b1 = bias[col + 1];
            float* pA = C + (size_t)rowA * N + col;
            float* pB = C + (size_t)rowB * N + col;
            if (MODE == 0) {
                *reinterpret_cast<float2*>(pA) =
                    make_float2(acc[i][j][0] + b0, acc[i][j][1] + b1);
                *reinterpret_cast<float2*>(pB) =
                    make_float2(acc[i][j][2] + b0, acc[i][j][3] + b1);
            } else {
                *reinterpret_cast<float2*>(pA) =
                    make_float2(gA * (acc[i][j][0] + b0), gA * (acc[i][j][1] + b1));
                *reinterpret_cast<float2*>(pB) =
                    make_float2(gB * (acc[i][j][2] + b0), gB * (acc[i][j][3] + b1));
            }
        }
    }
}

// ---------------------------------------------------------------------------
// Combine: out = sum over experts of gated partials Y[e].
// ---------------------------------------------------------------------------
__global__ void combine_kernel(const float* __restrict__ Cbase,
                               float* __restrict__ out, int n4) {
    int i = blockIdx.x * blockDim.x + threadIdx.x;
    if (i >= n4) return;
    float4 s = make_float4(0.f, 0.f, 0.f, 0.f);
#pragma unroll
    for (int e = 0; e < E_; e++) {
        float4 v = *reinterpret_cast<const float4*>(Cbase + (size_t)e * ACT_STRIDE + i * 4);
        s.x += v.x; s.y += v.y; s.z += v.z; s.w += v.w;
    }
    reinterpret_cast<float4*>(out)[i] = s;
}

// ---------------------------------------------------------------------------
// Launch
// ---------------------------------------------------------------------------
extern "C" void kernel_launch(void* const* d_in, const int* in_sizes, int n_in,
                              void* d_out, int out_size) {
    const float* x  = (const float*)d_in[0];
    const float* Wg = (const float*)d_in[1];
    const float* bg = (const float*)d_in[2];
    const float* W1 = (const float*)d_in[3];
    const float* b1 = (const float*)d_in[4];
    const float* W2 = (const float*)d_in[5];
    const float* b2 = (const float*)d_in[6];
    const float* W3 = (const float*)d_in[7];
    const float* b3 = (const float*)d_in[8];
    const float* W4 = (const float*)d_in[9];
    const float* b4 = (const float*)d_in[10];
    const float* W5 = (const float*)d_in[11];
    const float* b5 = (const float*)d_in[12];
    float* out = (float*)d_out;

    void *pWh, *pX, *pA, *pC;
    cudaGetSymbolAddress(&pWh, g_Wh);
    cudaGetSymbolAddress(&pX, g_X);
    cudaGetSymbolAddress(&pA, g_A);
    cudaGetSymbolAddress(&pC, g_C);
    unsigned short* Wh = (unsigned short*)pWh;
    unsigned short* X = (unsigned short*)pX;
    unsigned short* A = (unsigned short*)pA;
    float* Cbuf = (float*)pC;

    cudaFuncSetAttribute(tc_gemm_single<0>, cudaFuncAttributeMaxDynamicSharedMemorySize, SGL_SMEM);
    cudaFuncSetAttribute(tc_gemm_single<1>, cudaFuncAttributeMaxDynamicSharedMemorySize, SGL_SMEM);

    // Per-expert layer offsets within g_Wh ([N,K] packed, stride WPE per expert)
    const size_t off1 = 0;
    const size_t off2 = off1 + (size_t)DIN_ * H_;
    const size_t off3 = off2 + (size_t)H_ * H_;
    const size_t off4 = off3 + (size_t)H_ * H_;
    const size_t off5 = off4 + (size_t)H_ * H_;

    const dim3 wblk(32, 8);
    const dim3 gridH(H_ / 128, B_ / 128, E_);
    const dim3 gridO(DOUT_ / 128, B_ / 128, E_);
    const dim3 gridM(B_, E_);

    // Launch order (ncu -s 5 -c 1 profiles index 5 = batched L1 GEMM):
    // 0 xconv, 1 wconv L1, 2 gate, 3 wconv L2, 4 wconv L3, 5 gemm L1,
    // 6 mish, 7 wconv L4, 8 wconv L5, 9 gemm L2, 10 mish, 11 gemm L3,
    // 12 mish, 13 gemm L4, 14 mish, 15 gemm L5, 16 combine.
    xconv_kernel<<<(B_ * DIN_ / 4 + 255) / 256, 256>>>(x, X, B_ * DIN_ / 4);
    wconv_hi<<<dim3(H_ / 32, DIN_ / 64, E_), wblk>>>(W1, Wh + off1, DIN_, H_);
    gate_kernel<<<B_ / 8, 256>>>(x, Wg, bg);
    wconv_hi<<<dim3(H_ / 32, H_ / 64, E_), wblk>>>(W2, Wh + off2, H_, H_);
    wconv_hi<<<dim3(H_ / 32, H_ / 64, E_), wblk>>>(W3, Wh + off3, H_, H_);

    tc_gemm_single<0><<<gridH, 256, SGL_SMEM>>>(X, Wh + off1, b1, Cbuf, H_, DIN_, 0);
    mish_ln_cvt_kernel<<<gridM, 256>>>(Cbuf, A);

    wconv_hi<<<dim3(H_ / 32, H_ / 64, E_), wblk>>>(W4, Wh + off4, H_, H_);
    wconv_hi<<<dim3(DOUT_ / 32, H_ / 64, E_), wblk>>>(W5, Wh + off5, H_, DOUT_);

    tc_gemm_single<0><<<gridH, 256, SGL_SMEM>>>(A, Wh + off2, b2, Cbuf, H_, H_, ACT_STRIDE);
    mish_ln_cvt_kernel<<<gridM, 256>>>(Cbuf, A);
    tc_gemm_single<0><<<gridH, 256, SGL_SMEM>>>(A, Wh + off3, b3, Cbuf, H_, H_, ACT_STRIDE);
    mish_ln_cvt_kernel<<<gridM, 256>>>(Cbuf, A);
    tc_gemm_single<0><<<gridH, 256, SGL_SMEM>>>(A, Wh + off4, b4, Cbuf, H_, H_, ACT_STRIDE);
    mish_ln_cvt_kernel<<<gridM, 256>>>(Cbuf, A);
    tc_gemm_single<1><<<gridO, 256, SGL_SMEM>>>(A, Wh + off5, b5, Cbuf, DOUT_, H_, ACT_STRIDE);

    combine_kernel<<<(B_ * DOUT_ / 4 + 255) / 256, 256>>>(Cbuf, out, B_ * DOUT_ / 4);
}

// round 15
// speedup vs baseline: 1.5566x; 1.0011x over previous
#include <cuda_runtime.h>
#include <cuda_fp16.h>
#include <math.h>
#include <stdint.h>

#define B_    8192
#define DIN_  1024
#define H_    2048
#define DOUT_ 1024
#define E_    8

// ---------------------------------------------------------------------------
// Scratch (allocation-free __device__ globals)
// ---------------------------------------------------------------------------
#define WPE 16777216ull  // weight elements per expert (5 layers, transposed [N,K])
#define ACT_STRIDE ((size_t)B_ * H_)    // per-expert activation stride (elems)
__device__ unsigned short g_Wh[WPE * E_];            // fp16 weights (all layers, all experts)
__device__ unsigned short g_X[(size_t)B_ * DIN_];    // fp16 input acts (shared)
__device__ unsigned short g_A[ACT_STRIDE * E_];      // fp16 per-expert activations
__device__ float g_C[ACT_STRIDE * E_];               // fp32 per-expert GEMM out / final Y
__device__ float g_gate[(size_t)B_ * E_];

// ---------------------------------------------------------------------------
// PTX helpers
// ---------------------------------------------------------------------------
__device__ __forceinline__ uint32_t smem_to_u32(const void* smem_ptr) {
    uint32_t addr;
    asm("{ .reg .u64 tmp; cvta.to.shared.u64 tmp, %1; cvt.u32.u64 %0, tmp; }"
        : "=r"(addr) : "l"(smem_ptr));
    return addr;
}

#define CP_ASYNC16(dst, src) \
    asm volatile("cp.async.cg.shared.global [%0], [%1], 16;" \
                 :: "r"((uint32_t)(dst)), "l"(src) : "memory")

__device__ __forceinline__ void ldsm_x4(uint32_t* r, uint32_t addr) {
    asm volatile("ldmatrix.sync.aligned.m8n8.x4.shared.b16 {%0,%1,%2,%3}, [%4];"
                 : "=r"(r[0]), "=r"(r[1]), "=r"(r[2]), "=r"(r[3]) : "r"(addr));
}

__device__ __forceinline__ void mma_f16(float* c, const uint32_t* a, const uint32_t* b) {
    asm volatile(
        "mma.sync.aligned.m16n8k16.row.col.f32.f16.f16.f32 "
        "{%0,%1,%2,%3}, {%4,%5,%6,%7}, {%8,%9}, {%0,%1,%2,%3};"
        : "+f"(c[0]), "+f"(c[1]), "+f"(c[2]), "+f"(c[3])
        : "r"(a[0]), "r"(a[1]), "r"(a[2]), "r"(a[3]), "r"(b[0]), "r"(b[1]));
}

// ---------------------------------------------------------------------------
// Gate: softmax(x @ Wg + bg) per row. One warp/row.
// ---------------------------------------------------------------------------
__global__ void gate_kernel(const float* __restrict__ x,
                            const float* __restrict__ Wg,
                            const float* __restrict__ bg) {
    int gwarp = (blockIdx.x * blockDim.x + threadIdx.x) >> 5;
    int lane  = threadIdx.x & 31;
    if (gwarp >= B_) return;
    const float* xr = x + (size_t)gwarp * DIN_;
    float acc[E_];
#pragma unroll
    for (int e = 0; e < E_; e++) acc[e] = 0.f;
    for (int i = lane; i < DIN_; i += 32) {
        float xv = xr[i];
        const float4* w4 = reinterpret_cast<const float4*>(Wg + (size_t)i * E_);
        float4 w0 = w4[0], w1 = w4[1];
        acc[0] += xv * w0.x; acc[1] += xv * w0.y;
        acc[2] += xv * w0.z; acc[3] += xv * w0.w;
        acc[4] += xv * w1.x; acc[5] += xv * w1.y;
        acc[6] += xv * w1.z; acc[7] += xv * w1.w;
    }
#pragma unroll
    for (int e = 0; e < E_; e++) {
#pragma unroll
        for (int o = 16; o > 0; o >>= 1)
            acc[e] += __shfl_xor_sync(0xffffffffu, acc[e], o);
    }
    if (lane == 0) {
        float mx = -1e30f;
#pragma unroll
        for (int e = 0; e < E_; e++) { acc[e] += bg[e]; mx = fmaxf(mx, acc[e]); }
        float s = 0.f;
#pragma unroll
        for (int e = 0; e < E_; e++) { acc[e] = expf(acc[e] - mx); s += acc[e]; }
        float inv = 1.f / s;
#pragma unroll
        for (int e = 0; e < E_; e++) g_gate[(size_t)gwarp * E_ + e] = acc[e] * inv;
    }
}

// ---------------------------------------------------------------------------
// Weight convert+transpose, batched over experts (blockIdx.z):
// W [E,K,N] fp32 -> [E][N,K] fp16 (per-expert stride WPE on output).
// ---------------------------------------------------------------------------
__global__ void wconv_hi(const float* __restrict__ Wbase,
                         unsigned short* __restrict__ Whbase,
                         int K, int N) {
    __shared__ float t[64][33];
    const float* W = Wbase + (size_t)blockIdx.z * K * N;
    unsigned short* Wh = Whbase + (size_t)blockIdx.z * WPE;
    const int n0 = blockIdx.x * 32, k0 = blockIdx.y * 64;
    const int tx = threadIdx.x, ty = threadIdx.y;  // 32x8
#pragma unroll
    for (int r = 0; r < 8; r++) {
        int k = ty + r * 8;
        t[k][tx] = W[(size_t)(k0 + k) * N + n0 + tx];
    }
    __syncthreads();
#pragma unroll
    for (int r = 0; r < 4; r++) {
        int n = ty + r * 8;
        __half h0 = __float2half_rn(t[2 * tx][n]);
        __half h1 = __float2half_rn(t[2 * tx + 1][n]);
        size_t o = (size_t)(n0 + n) * K + k0 + 2 * tx;
        *reinterpret_cast<ushort2*>(&Wh[o]) =
            make_ushort2(__half_as_ushort(h0), __half_as_ushort(h1));
    }
}

// ---------------------------------------------------------------------------
// Merged weight convert for the three H x H layers (W2, W3, W4):
// blockIdx.z in [0, 3*E): layer = z / E, expert = z % E.
// Output layer l goes to Whbase + loff[l] + expert*WPE.
// ---------------------------------------------------------------------------
__global__ void wconv_hi3(const float* __restrict__ W2b,
                          const float* __restrict__ W3b,
                          const float* __restrict__ W4b,
                          unsigned short* __restrict__ Whbase,
                          size_t off2, size_t off3, size_t off4) {
    __shared__ float t[64][33];
    const int lz = blockIdx.z / E_;
    const int ez = blockIdx.z - lz * E_;
    const float* Wsrc = (lz == 0) ? W2b : (lz == 1) ? W3b : W4b;
    const size_t loff = (lz == 0) ? off2 : (lz == 1) ? off3 : off4;
    const float* W = Wsrc + (size_t)ez * H_ * H_;
    unsigned short* Wh = Whbase + loff + (size_t)ez * WPE;
    const int K = H_, N = H_;
    const int n0 = blockIdx.x * 32, k0 = blockIdx.y * 64;
    const int tx = threadIdx.x, ty = threadIdx.y;  // 32x8
#pragma unroll
    for (int r = 0; r < 8; r++) {
        int k = ty + r * 8;
        t[k][tx] = W[(size_t)(k0 + k) * N + n0 + tx];
    }
    __syncthreads();
#pragma unroll
    for (int r = 0; r < 4; r++) {
        int n = ty + r * 8;
        __half h0 = __float2half_rn(t[2 * tx][n]);
        __half h1 = __float2half_rn(t[2 * tx + 1][n]);
        size_t o = (size_t)(n0 + n) * K + k0 + 2 * tx;
        *reinterpret_cast<ushort2*>(&Wh[o]) =
            make_ushort2(__half_as_ushort(h0), __half_as_ushort(h1));
    }
}

// ---------------------------------------------------------------------------
// x convert: fp32 -> fp16.
// ---------------------------------------------------------------------------
__global__ void xconv_kernel(const float* __restrict__ x,
                             unsigned short* __restrict__ X, int n4) {
    int i = blockIdx.x * blockDim.x + threadIdx.x;
    if (i >= n4) return;
    float4 v = reinterpret_cast<const float4*>(x)[i];
    ushort4 o;
    o.x = __half_as_ushort(__float2half_rn(v.x));
    o.y = __half_as_ushort(__float2half_rn(v.y));
    o.z = __half_as_ushort(__float2half_rn(v.z));
    o.w = __half_as_ushort(__float2half_rn(v.w));
    reinterpret_cast<ushort4*>(X)[i] = o;
}

// ---------------------------------------------------------------------------
// Fast mish: tanh(softplus(h)) = (u^2+2u)/(u^2+2u+2), u = e^h.
// ---------------------------------------------------------------------------
__device__ __forceinline__ float mish_fast(float h) {
    if (h > 20.f) return h;
    float u = __expf(h);
    float w = u * (u + 2.f);
    return h * __fdividef(w, w + 2.f);
}

// ---------------------------------------------------------------------------
// mish + LayerNorm + fp16 convert, batched over experts (blockIdx.y).
// Row of H_=2048, 256 threads.
// ---------------------------------------------------------------------------
__global__ void mish_ln_cvt_kernel(const float* __restrict__ Cbase,
                                   unsigned short* __restrict__ Abase) {
    __shared__ float sred[64];
    const int t = threadIdx.x;
    const size_t rowoff = ((size_t)blockIdx.y * B_ + blockIdx.x) * H_;
    const float4* p = reinterpret_cast<const float4*>(Cbase + rowoff);
    float4 v0 = p[t], v1 = p[t + 256];
    float vals[8] = {v0.x, v0.y, v0.z, v0.w, v1.x, v1.y, v1.z, v1.w};
    float s = 0.f, q = 0.f;
#pragma unroll
    for (int i = 0; i < 8; i++) {
        float m = mish_fast(vals[i]);
        vals[i] = m;
        s += m;
        q += m * m;
    }
#pragma unroll
    for (int o = 16; o > 0; o >>= 1) {
        s += __shfl_xor_sync(0xffffffffu, s, o);
        q += __shfl_xor_sync(0xffffffffu, q, o);
    }
    const int w = t >> 5;
    if ((t & 31) == 0) { sred[w] = s; sred[w + 32] = q; }
    __syncthreads();
    if (t < 32) {
        float rs = (t < 8) ? sred[t] : 0.f;
        float rq = (t < 8) ? sred[t + 32] : 0.f;
#pragma unroll
        for (int o = 4; o > 0; o >>= 1) {
            rs += __shfl_xor_sync(0xffffffffu, rs, o);
            rq += __shfl_xor_sync(0xffffffffu, rq, o);
        }
        if (t == 0) { sred[0] = rs; sred[32] = rq; }
    }
    __syncthreads();
    const float mu = sred[0] * (1.f / H_);
    const float var = sred[32] * (1.f / H_) - mu * mu;
    const float inv = rsqrtf(var + 1e-5f);
    unsigned short h8[8];
#pragma unroll
    for (int i = 0; i < 8; i++)
        h8[i] = __half_as_ushort(__float2half_rn((vals[i] - mu) * inv));
    ushort4* oa = reinterpret_cast<ushort4*>(Abase + rowoff);
    oa[t]       = make_ushort4(h8[0], h8[1], h8[2], h8[3]);
    oa[t + 256] = make_ushort4(h8[4], h8[5], h8[6], h8[7]);
}

// ---------------------------------------------------------------------------
// GEMM geometry (validated R12 config): CTA 128x128, 8 warps (2 M x 4 N),
// warp tile 64x32, K-chunk 32, STRIDE 80B, 2 CTAs/SM. Pipeline depth 5.
// ---------------------------------------------------------------------------
#define STRIDE_B 80                       // padded row stride in bytes
#define MAT_BYTES (128 * STRIDE_B)        // 10240
#define STAGE_BYTES (2 * MAT_BYTES)       // 20480 (A, Wh)
#define NSTAGE 5
#define SGL_SMEM (NSTAGE * STAGE_BYTES)   // 102400

__device__ __forceinline__ void copy_stage2(uint32_t st, int tid, int kc, int K,
                                            const unsigned short* a,
                                            const unsigned short* bh) {
    const unsigned short* srcs[2] = {a, bh};
#pragma unroll
    for (int m = 0; m < 2; m++) {
#pragma unroll
        for (int q = 0; q < 2; q++) {
            int c = tid * 2 + q;          // 0..511
            int row = c >> 2;             // 0..127
            int kch = c & 3;              // 16B chunk within the 64B row
            uint32_t dst = st + m * MAT_BYTES + row * STRIDE_B + kch * 16;
            const unsigned short* src = srcs[m] + (size_t)row * K + kc * 32 + kch * 8;
            CP_ASYNC16(dst, src);
        }
    }
    asm volatile("cp.async.commit_group;" ::: "memory");
}

// ---------------------------------------------------------------------------
// Single-pass fp16 GEMM, batched over experts (blockIdx.z).
// MODE 0: C[z] = A[z]@W[z]^T + bias[z]
// MODE 1: C[z] = gate[row,z] * (A[z]@W[z]^T + bias[z])
// strideA = 0 lets all experts share one input (L1 / X).
// ---------------------------------------------------------------------------
template <int MODE>
__global__ __launch_bounds__(256, 2)
void tc_gemm_single(const unsigned short* __restrict__ Ag,
                    const unsigned short* __restrict__ Wg,
                    const float* __restrict__ biasg, float* __restrict__ Cg,
                    int N, int K, size_t strideA) {
    extern __shared__ __align__(16) char dynsmem[];
    const uint32_t sbase = smem_to_u32(dynsmem);
    const int tid = threadIdx.x;
    const int wid = tid >> 5, lane = tid & 31;
    const int wm = wid & 1, wn = wid >> 1;   // 2 warps M x 4 warps N
    const int KT = K >> 5;                   // 32 fp16 per chunk (KT >= 32)
    const int ez = blockIdx.z;

    const unsigned short* a  = Ag + (size_t)ez * strideA + (size_t)(blockIdx.y * 128) * K;
    const unsigned short* bh = Wg + (size_t)ez * WPE + (size_t)(blockIdx.x * 128) * K;
    const float* bias = biasg + (size_t)ez * N;
    float* C = Cg + (size_t)ez * ACT_STRIDE;

    float acc[4][4][4];
#pragma unroll
    for (int i = 0; i < 4; i++)
#pragma unroll
        for (int j = 0; j < 4; j++)
#pragma unroll
            for (int q = 0; q < 4; q++) acc[i][j][q] = 0.f;

    // Prologue: fill 4 of 5 stages
    copy_stage2(sbase + 0 * STAGE_BYTES, tid, 0, K, a, bh);
    copy_stage2(sbase + 1 * STAGE_BYTES, tid, 1, K, a, bh);
    copy_stage2(sbase + 2 * STAGE_BYTES, tid, 2, K, a, bh);
    copy_stage2(sbase + 3 * STAGE_BYTES, tid, 3, K, a, bh);

    const uint32_t a_row = wm * 64 + (lane & 15);
    const uint32_t a_koff = (lane >> 4) * 16;
    const uint32_t b_row = wn * 32 + (lane >> 4) * 8 + (lane & 7);
    const uint32_t b_koff = ((lane >> 3) & 1) * 16;

    int scur = 0;   // kc % 5
    int sref = 4;   // (kc+4) % 5
    for (int kc = 0; kc < KT; kc++) {
        if (kc + 3 < KT)      asm volatile("cp.async.wait_group 3;" ::: "memory");
        else if (kc + 2 < KT) asm volatile("cp.async.wait_group 2;" ::: "memory");
        else if (kc + 1 < KT) asm volatile("cp.async.wait_group 1;" ::: "memory");
        else                  asm volatile("cp.async.wait_group 0;" ::: "memory");
        __syncthreads();
        // Stage (kc-1)%5 == (kc+4)%5 fully consumed before the barrier -> refill.
        if (kc + 4 < KT)
            copy_stage2(sbase + sref * STAGE_BYTES, tid, kc + 4, K, a, bh);

        const uint32_t st = sbase + scur * STAGE_BYTES;
#pragma unroll
        for (int h = 0; h < 2; h++) {     // two k16 halves of the 32-elem chunk
            const uint32_t kbyte = h * 32;
            uint32_t fa[16], fbh[8];
#pragma unroll
            for (int i = 0; i < 4; i++)
                ldsm_x4(&fa[i * 4], st + (a_row + i * 16) * STRIDE_B + kbyte + a_koff);
#pragma unroll
            for (int p = 0; p < 2; p++)
                ldsm_x4(&fbh[p * 4],
                        st + MAT_BYTES + (b_row + p * 16) * STRIDE_B + kbyte + b_koff);
#pragma unroll
            for (int i = 0; i < 4; i++)
#pragma unroll
                for (int j = 0; j < 4; j++)
                    mma_f16(acc[i][j], &fa[i * 4], &fbh[(j >> 1) * 4 + (j & 1) * 2]);
        }
        scur = (scur == 4) ? 0 : scur + 1;
        sref = (sref == 4) ? 0 : sref + 1;
    }

    const int r0 = blockIdx.y * 128 + wm * 64 + (lane >> 2);
    const int cbase = blockIdx.x * 128 + wn * 32 + (lane & 3) * 2;
#pragma unroll
    for (int i = 0; i < 4; i++) {
        const int rowA = r0 + i * 16;
        const int rowB = rowA + 8;
        float gA = 1.f, gB = 1.f;
        if (MODE == 1) {
            gA = g_gate[(size_t)rowA * E_ + ez];
            gB = g_gate[(size_t)rowB * E_ + ez];
        }
#pragma unroll
        for (int j = 0; j < 4; j++) {
            const int col = cbase + j * 8;
            float b0 = bias[col], b1 = bias[col + 1];
            float* pA = C + (size_t)rowA * N + col;
            float* pB = C + (size_t)rowB * N + col;
            if (MODE == 0) {
                *reinterpret_cast<float2*>(pA) =
                    make_float2(acc[i][j][0] + b0, acc[i][j][1] + b1);
                *reinterpret_cast<float2*>(pB) =
                    make_float2(acc[i][j][2] + b0, acc[i][j][3] + b1);
            } else {
                *reinterpret_cast<float2*>(pA) =
                    make_float2(gA * (acc[i][j][0] + b0), gA * (acc[i][j][1] + b1));
                *reinterpret_cast<float2*>(pB) =
                    make_float2(gB * (acc[i][j][2] + b0), gB * (acc[i][j][3] + b1));
            }
        }
    }
}

// ---------------------------------------------------------------------------
// Combine: out = sum over experts of gated partials Y[e].
// ---------------------------------------------------------------------------
__global__ void combine_kernel(const float* __restrict__ Cbase,
                               float* __restrict__ out, int n4) {
    int i = blockIdx.x * blockDim.x + threadIdx.x;
    if (i >= n4) return;
    float4 s = make_float4(0.f, 0.f, 0.f, 0.f);
#pragma unroll
    for (int e = 0; e < E_; e++) {
        float4 v = *reinterpret_cast<const float4*>(Cbase + (size_t)e * ACT_STRIDE + i * 4);
        s.x += v.x; s.y += v.y; s.z += v.z; s.w += v.w;
    }
    reinterpret_cast<float4*>(out)[i] = s;
}

// ---------------------------------------------------------------------------
// Launch
// ---------------------------------------------------------------------------
extern "C" void kernel_launch(void* const* d_in, const int* in_sizes, int n_in,
                              void* d_out, int out_size) {
    const float* x  = (const float*)d_in[0];
    const float* Wg = (const float*)d_in[1];
    const float* bg = (const float*)d_in[2];
    const float* W1 = (const float*)d_in[3];
    const float* b1 = (const float*)d_in[4];
    const float* W2 = (const float*)d_in[5];
    const float* b2 = (const float*)d_in[6];
    const float* W3 = (const float*)d_in[7];
    const float* b3 = (const float*)d_in[8];
    const float* W4 = (const float*)d_in[9];
    const float* b4 = (const float*)d_in[10];
    const float* W5 = (const float*)d_in[11];
    const float* b5 = (const float*)d_in[12];
    float* out = (float*)d_out;

    void *pWh, *pX, *pA, *pC;
    cudaGetSymbolAddress(&pWh, g_Wh);
    cudaGetSymbolAddress(&pX, g_X);
    cudaGetSymbolAddress(&pA, g_A);
    cudaGetSymbolAddress(&pC, g_C);
    unsigned short* Wh = (unsigned short*)pWh;
    unsigned short* X = (unsigned short*)pX;
    unsigned short* A = (unsigned short*)pA;
    float* Cbuf = (float*)pC;

    cudaFuncSetAttribute(tc_gemm_single<0>, cudaFuncAttributeMaxDynamicSharedMemorySize, SGL_SMEM);
    cudaFuncSetAttribute(tc_gemm_single<1>, cudaFuncAttributeMaxDynamicSharedMemorySize, SGL_SMEM);

    // Per-expert layer offsets within g_Wh ([N,K] packed, stride WPE per expert)
    const size_t off1 = 0;
    const size_t off2 = off1 + (size_t)DIN_ * H_;
    const size_t off3 = off2 + (size_t)H_ * H_;
    const size_t off4 = off3 + (size_t)H_ * H_;
    const size_t off5 = off4 + (size_t)H_ * H_;

    const dim3 wblk(32, 8);
    const dim3 gridH(H_ / 128, B_ / 128, E_);
    const dim3 gridO(DOUT_ / 128, B_ / 128, E_);
    const dim3 gridM(B_, E_);

    // Launch order (ncu -s 5 -c 1 profiles index 5 = batched L1 GEMM):
    // 0 xconv, 1 wconv L1, 2 gate, 3 wconv L2+L3+L4 (merged), 4 wconv L5,
    // 5 gemm L1, 6 mish, 7 gemm L2, 8 mish, 9 gemm L3, 10 mish,
    // 11 gemm L4, 12 mish, 13 gemm L5, 14 combine.
    xconv_kernel<<<(B_ * DIN_ / 4 + 255) / 256, 256>>>(x, X, B_ * DIN_ / 4);
    wconv_hi<<<dim3(H_ / 32, DIN_ / 64, E_), wblk>>>(W1, Wh + off1, DIN_, H_);
    gate_kernel<<<B_ / 8, 256>>>(x, Wg, bg);
    wconv_hi3<<<dim3(H_ / 32, H_ / 64, 3 * E_), wblk>>>(W2, W3, W4, Wh, off2, off3, off4);
    wconv_hi<<<dim3(DOUT_ / 32, H_ / 64, E_), wblk>>>(W5, Wh + off5, H_, DOUT_);

    tc_gemm_single<0><<<gridH, 256, SGL_SMEM>>>(X, Wh + off1, b1, Cbuf, H_, DIN_, 0);
    mish_ln_cvt_kernel<<<gridM, 256>>>(Cbuf, A);
    tc_gemm_single<0><<<gridH, 256, SGL_SMEM>>>(A, Wh + off2, b2, Cbuf, H_, H_, ACT_STRIDE);
    mish_ln_cvt_kernel<<<gridM, 256>>>(Cbuf, A);
    tc_gemm_single<0><<<gridH, 256, SGL_SMEM>>>(A, Wh + off3, b3, Cbuf, H_, H_, ACT_STRIDE);
    mish_ln_cvt_kernel<<<gridM, 256>>>(Cbuf, A);
    tc_gemm_single<0><<<gridH, 256, SGL_SMEM>>>(A, Wh + off4, b4, Cbuf, H_, H_, ACT_STRIDE);
    mish_ln_cvt_kernel<<<gridM, 256>>>(Cbuf, A);
    tc_gemm_single<1><<<gridO, 256, SGL_SMEM>>>(A, Wh + off5, b5, Cbuf, DOUT_, H_, ACT_STRIDE);

    combine_kernel<<<(B_ * DOUT_ / 4 + 255) / 256, 256>>>(Cbuf, out, B_ * DOUT_ / 4);
}